// round 2
// baseline (speedup 1.0000x reference)
#include <cuda_runtime.h>

#define NN 100000
#define DH 128
#define CC 64

// ---------------- device scratch (static, no allocs) ----------------
__device__ float    g_m[(size_t)NN * DH];    // m = h @ W^T
__device__ float    g_acc[(size_t)NN * DH];  // scatter accumulator
__device__ float    g_h[(size_t)NN * DH];    // layer activations
__device__ float    g_dis[NN];               // deg^{-1/2}
__device__ unsigned g_deg[NN];
__device__ float    g_Wt1[DH * DH];          // W1 transposed: Wt[k][j]
__device__ float    g_Wt2[DH * DH];
__device__ float    g_WtL[DH * CC];
__device__ int      g_is64;                  // edge_index dtype flag

// ---------------- small setup kernels ----------------
__global__ void k_init(unsigned* deg) {
    int i = blockIdx.x * blockDim.x + threadIdx.x;
    if (i < NN) deg[i] = 1u;                 // self-loop contributes 1 to degree
    if (i == 0) g_is64 = 1;
}

// If edge_index is int64 (values < 2^31), every odd 32-bit word is 0.
__global__ void k_detect(const int* __restrict__ w) {
    int i = threadIdx.x;                     // 256 threads, probe 256 odd words
    if (w[2 * i + 1] != 0) g_is64 = 0;
}

__device__ __forceinline__ int edge_idx(const void* ei, long long i) {
    if (g_is64) return (int)((const long long*)ei)[i];
    return ((const int*)ei)[i];
}

__global__ void k_deg(const void* __restrict__ ei, long long E, unsigned* deg) {
    long long i = (long long)blockIdx.x * blockDim.x + threadIdx.x;
    if (i < E) atomicAdd(&deg[edge_idx(ei, E + i)], 1u);   // dst half
}

__global__ void k_dis(const unsigned* __restrict__ deg, float* __restrict__ dis) {
    int i = blockIdx.x * blockDim.x + threadIdx.x;
    if (i < NN) dis[i] = rsqrtf((float)deg[i]);            // deg >= 1 always
}

// W[r][c] (row-major, r = out col, c = k) -> Wt[c*R + r]
__global__ void k_transpose(const float* __restrict__ W, float* __restrict__ Wt,
                            int R, int C) {
    int i = blockIdx.x * blockDim.x + threadIdx.x;
    if (i < R * C) {
        int r = i / C, c = i % C;
        Wt[c * R + r] = W[i];
    }
}

// ---------------- GEMM: m = hin @ W^T (K = 128 fixed) ----------------
// Tile: 64 nodes x COLS. 256 threads; each thread: NPT nodes x 4 cols.
// hin tile staged in smem (broadcast reads), Wt streamed via L1 (fits, 64KB).
template <int COLS, int NPT, bool HEAD>
__global__ __launch_bounds__(256) void k_gemm(
    const float* __restrict__ hin, const float* __restrict__ Wt,
    const float* __restrict__ aux,   // HEAD: bias[COLS]; else dis[NN]
    float* __restrict__ mo,          // HEAD: output; else g_m
    float* __restrict__ ao)          // !HEAD: g_acc (self-loop seeded)
{
    __shared__ float Hs[64][DH];
    const int t = threadIdx.x;
    const int node0 = blockIdx.x * 64;

    const float4* hin4 = (const float4*)(hin + (size_t)node0 * DH);
    #pragma unroll
    for (int i = t; i < 64 * (DH / 4); i += 256) {
        int row = i >> 5;
        float4 v = make_float4(0.f, 0.f, 0.f, 0.f);
        if (node0 + row < NN) v = hin4[i];
        ((float4*)Hs)[i] = v;
    }
    __syncthreads();

    constexpr int CG = COLS / 4;
    const int colg = t % CG;
    const int nb = (t / CG) * NPT;

    float acc[NPT][4];
    #pragma unroll
    for (int n = 0; n < NPT; n++)
        acc[n][0] = acc[n][1] = acc[n][2] = acc[n][3] = 0.f;

    const float4* Wt4 = (const float4*)Wt;
    #pragma unroll 8
    for (int k = 0; k < DH; k++) {
        float4 w = __ldg(&Wt4[k * CG + colg]);
        #pragma unroll
        for (int n = 0; n < NPT; n++) {
            float hv = Hs[nb + n][k];
            acc[n][0] = fmaf(hv, w.x, acc[n][0]);
            acc[n][1] = fmaf(hv, w.y, acc[n][1]);
            acc[n][2] = fmaf(hv, w.z, acc[n][2]);
            acc[n][3] = fmaf(hv, w.w, acc[n][3]);
        }
    }

    #pragma unroll
    for (int n = 0; n < NPT; n++) {
        int node = node0 + nb + n;
        if (node >= NN) break;
        float4 r = make_float4(acc[n][0], acc[n][1], acc[n][2], acc[n][3]);
        if (HEAD) {
            float4 bb = __ldg(&((const float4*)aux)[colg]);
            r.x += bb.x; r.y += bb.y; r.z += bb.z; r.w += bb.w;
            ((float4*)(mo + (size_t)node * COLS))[colg] = r;
        } else {
            ((float4*)(mo + (size_t)node * COLS))[colg] = r;
            float d = __ldg(&aux[node]);
            float d2 = d * d;                // self-loop norm = dis[i]^2
            float4 a = make_float4(r.x * d2, r.y * d2, r.z * d2, r.w * d2);
            ((float4*)(ao + (size_t)node * COLS))[colg] = a;
        }
    }
}

// ---------------- edge scatter: acc[d] += m[s] * dis[s]*dis[d] ----------------
// One warp per edge; one float4 per lane; vectorized RED (4x fewer atomics).
__global__ __launch_bounds__(256) void k_scatter(
    const void* __restrict__ ei, long long E,
    const float* __restrict__ dis, const float* __restrict__ m,
    float* __restrict__ acc)
{
    long long gw = ((long long)blockIdx.x * blockDim.x + threadIdx.x) >> 5;
    int lane = threadIdx.x & 31;
    if (gw >= E) return;
    int s = edge_idx(ei, gw);
    int d = edge_idx(ei, E + gw);
    float nrm = dis[s] * dis[d];
    float4 v = ((const float4*)(m + (size_t)s * DH))[lane];
    float* p = acc + (size_t)d * DH + (lane << 2);
    asm volatile("red.global.add.v4.f32 [%0], {%1, %2, %3, %4};"
                 :: "l"(p), "f"(v.x * nrm), "f"(v.y * nrm),
                    "f"(v.z * nrm), "f"(v.w * nrm)
                 : "memory");
}

// ---------------- epilogue: h = relu(acc + b) + residual ----------------
__global__ void k_epi(const float* __restrict__ acc, const float* __restrict__ b,
                      const float* __restrict__ hres, float* __restrict__ ho) {
    long long i = (long long)blockIdx.x * blockDim.x + threadIdx.x;
    if (i >= (long long)NN * (DH / 4)) return;
    float4 a = ((const float4*)acc)[i];
    float4 bb = ((const float4*)b)[(int)(i & 31)];
    float4 r = ((const float4*)hres)[i];
    float4 o;
    o.x = fmaxf(a.x + bb.x, 0.f) + r.x;
    o.y = fmaxf(a.y + bb.y, 0.f) + r.y;
    o.z = fmaxf(a.z + bb.z, 0.f) + r.z;
    o.w = fmaxf(a.w + bb.w, 0.f) + r.w;
    ((float4*)ho)[i] = o;
}

// ---------------- launch ----------------
extern "C" void kernel_launch(void* const* d_in, const int* in_sizes, int n_in,
                              void* d_out, int out_size) {
    const float* x  = (const float*)d_in[0];
    const void*  ei = d_in[1];
    const float* W1 = (const float*)d_in[2];
    const float* b1 = (const float*)d_in[3];
    const float* W2 = (const float*)d_in[4];
    const float* b2 = (const float*)d_in[5];
    const float* Wl = (const float*)d_in[6];
    const float* bl = (const float*)d_in[7];
    long long E = (long long)in_sizes[1] / 2;

    float *m, *acc, *h, *dis, *Wt1, *Wt2, *WtL;
    unsigned* deg;
    cudaGetSymbolAddress((void**)&m,   g_m);
    cudaGetSymbolAddress((void**)&acc, g_acc);
    cudaGetSymbolAddress((void**)&h,   g_h);
    cudaGetSymbolAddress((void**)&dis, g_dis);
    cudaGetSymbolAddress((void**)&deg, g_deg);
    cudaGetSymbolAddress((void**)&Wt1, g_Wt1);
    cudaGetSymbolAddress((void**)&Wt2, g_Wt2);
    cudaGetSymbolAddress((void**)&WtL, g_WtL);

    // setup
    k_init<<<(NN + 255) / 256, 256>>>(deg);
    k_detect<<<1, 256>>>((const int*)ei);
    k_deg<<<(unsigned)((E + 255) / 256), 256>>>(ei, E, deg);
    k_dis<<<(NN + 255) / 256, 256>>>(deg, dis);
    k_transpose<<<(DH * DH + 255) / 256, 256>>>(W1, Wt1, DH, DH);
    k_transpose<<<(DH * DH + 255) / 256, 256>>>(W2, Wt2, DH, DH);
    k_transpose<<<(CC * DH + 255) / 256, 256>>>(Wl, WtL, CC, DH);

    const int gblocks = (NN + 63) / 64;
    const unsigned sblocks = (unsigned)((E + 7) / 8);   // 8 warp-edges / block
    const int eblocks = (NN * (DH / 4) + 255) / 256;

    // layer 1
    k_gemm<DH, 8, false><<<gblocks, 256>>>(x, Wt1, dis, m, acc);
    k_scatter<<<sblocks, 256>>>(ei, E, dis, m, acc);
    k_epi<<<eblocks, 256>>>(acc, b1, x, h);

    // layer 2
    k_gemm<DH, 8, false><<<gblocks, 256>>>(h, Wt2, dis, m, acc);
    k_scatter<<<sblocks, 256>>>(ei, E, dis, m, acc);
    k_epi<<<eblocks, 256>>>(acc, b2, h, h);   // elementwise in-place: safe

    // head
    k_gemm<CC, 4, true><<<gblocks, 256>>>(h, WtL, bl, (float*)d_out, nullptr);
}

// round 3
// speedup vs baseline: 1.7865x; 1.7865x over previous
#include <cuda_runtime.h>

#define NN 100000
#define EE 1600000
#define DH 128
#define CC 64
#define NB_SCAN 98          // ceil(NN/1024)

// ---------------- device scratch (static, no allocs) ----------------
__device__ float    g_m[(size_t)NN * DH];    // m = h @ W^T
__device__ float    g_h[(size_t)NN * DH];    // layer activations
__device__ float    g_dis[NN];               // deg^{-1/2}
__device__ unsigned g_deg[NN];               // 1 + in-degree
__device__ unsigned g_part[NN];              // scan partials
__device__ unsigned g_bsum[NB_SCAN];
__device__ unsigned g_off[NN + 1];           // CSR offsets
__device__ unsigned g_curs[NN];              // placement cursors
__device__ int      g_csr_src[EE];
__device__ float    g_csr_nrm[EE];
__device__ float    g_Wt1[DH * DH];          // W transposed: Wt[k][j]
__device__ float    g_Wt2[DH * DH];
__device__ float    g_WtL[DH * CC];
__device__ int      g_is64;

// ---------------- setup ----------------
__global__ void k_init(unsigned* deg) {
    int i = blockIdx.x * blockDim.x + threadIdx.x;
    if (i < NN) deg[i] = 1u;                 // self-loop
    if (i == 0) g_is64 = 1;
}

// int64 edge values < 2^31 -> all odd 32-bit words are zero
__global__ void k_detect(const int* __restrict__ w) {
    if (w[2 * threadIdx.x + 1] != 0) g_is64 = 0;
}

__device__ __forceinline__ int edge_idx(const void* ei, long long i) {
    if (g_is64) return (int)((const long long*)ei)[i];
    return ((const int*)ei)[i];
}

__global__ void k_deg(const void* __restrict__ ei, long long E, unsigned* deg) {
    long long i = (long long)blockIdx.x * blockDim.x + threadIdx.x;
    if (i < E) atomicAdd(&deg[edge_idx(ei, E + i)], 1u);
}

__global__ void k_dis(const unsigned* __restrict__ deg, float* __restrict__ dis) {
    int i = blockIdx.x * blockDim.x + threadIdx.x;
    if (i < NN) dis[i] = rsqrtf((float)deg[i]);
}

__global__ void k_transpose(const float* __restrict__ W, float* __restrict__ Wt,
                            int R, int C) {
    int i = blockIdx.x * blockDim.x + threadIdx.x;
    if (i < R * C) {
        int r = i / C, c = i % C;
        Wt[c * R + r] = W[i];
    }
}

// ---------------- CSR build: scan of (deg-1) ----------------
__global__ __launch_bounds__(1024) void k_scan1(const unsigned* __restrict__ deg,
                                                unsigned* __restrict__ part,
                                                unsigned* __restrict__ bsum) {
    __shared__ unsigned ws[32];
    int t = threadIdx.x;
    int i = blockIdx.x * 1024 + t;
    unsigned x = (i < NN) ? (deg[i] - 1u) : 0u;
    #pragma unroll
    for (int o = 1; o < 32; o <<= 1) {
        unsigned y = __shfl_up_sync(~0u, x, o);
        if ((t & 31) >= o) x += y;
    }
    if ((t & 31) == 31) ws[t >> 5] = x;
    __syncthreads();
    if (t < 32) {
        unsigned w = ws[t];
        #pragma unroll
        for (int o = 1; o < 32; o <<= 1) {
            unsigned y = __shfl_up_sync(~0u, w, o);
            if (t >= o) w += y;
        }
        ws[t] = w;
    }
    __syncthreads();
    if (t >= 32) x += ws[(t >> 5) - 1];
    if (i < NN) part[i] = x;
    if (t == 1023) bsum[blockIdx.x] = x;
}

__global__ void k_scan2(unsigned* __restrict__ bsum) {
    __shared__ unsigned s[NB_SCAN];
    int t = threadIdx.x;
    if (t < NB_SCAN) s[t] = bsum[t];
    __syncthreads();
    if (t == 0) {                            // exclusive scan, tiny
        unsigned run = 0;
        for (int k = 0; k < NB_SCAN; k++) {
            unsigned v = s[k];
            s[k] = run;
            run += v;
        }
    }
    __syncthreads();
    if (t < NB_SCAN) bsum[t] = s[t];
}

__global__ void k_scan3(const unsigned* __restrict__ deg,
                        const unsigned* __restrict__ part,
                        const unsigned* __restrict__ bsum,
                        unsigned* __restrict__ off,
                        unsigned* __restrict__ curs,
                        long long E) {
    int i = blockIdx.x * blockDim.x + threadIdx.x;
    if (i < NN) {
        unsigned incl = part[i] + bsum[i >> 10];
        unsigned excl = incl - (deg[i] - 1u);
        off[i]  = excl;
        curs[i] = excl;
    }
    if (i == 0) off[NN] = (unsigned)E;
}

__global__ void k_place(const void* __restrict__ ei, long long E,
                        const float* __restrict__ dis,
                        unsigned* __restrict__ curs,
                        int* __restrict__ csrc, float* __restrict__ cnrm) {
    long long i = (long long)blockIdx.x * blockDim.x + threadIdx.x;
    if (i >= E) return;
    int s = edge_idx(ei, i);
    int d = edge_idx(ei, E + i);
    unsigned pos = atomicAdd(&curs[d], 1u);
    csrc[pos] = s;
    cnrm[pos] = dis[s] * dis[d];
}

// ---------------- GEMM: m = hin @ W^T (K = 128 fixed) ----------------
template <int COLS, int NPT, bool HEAD>
__global__ __launch_bounds__(256) void k_gemm(
    const float* __restrict__ hin, const float* __restrict__ Wt,
    const float* __restrict__ bias, float* __restrict__ mo)
{
    __shared__ float Hs[64][DH];
    const int t = threadIdx.x;
    const int node0 = blockIdx.x * 64;

    const float4* hin4 = (const float4*)(hin + (size_t)node0 * DH);
    #pragma unroll
    for (int i = t; i < 64 * (DH / 4); i += 256) {
        int row = i >> 5;
        float4 v = make_float4(0.f, 0.f, 0.f, 0.f);
        if (node0 + row < NN) v = hin4[i];
        ((float4*)Hs)[i] = v;
    }
    __syncthreads();

    constexpr int CG = COLS / 4;
    const int colg = t % CG;
    const int nb = (t / CG) * NPT;

    float acc[NPT][4];
    #pragma unroll
    for (int n = 0; n < NPT; n++)
        acc[n][0] = acc[n][1] = acc[n][2] = acc[n][3] = 0.f;

    const float4* Wt4 = (const float4*)Wt;
    #pragma unroll 8
    for (int k = 0; k < DH; k++) {
        float4 w = __ldg(&Wt4[k * CG + colg]);
        #pragma unroll
        for (int n = 0; n < NPT; n++) {
            float hv = Hs[nb + n][k];
            acc[n][0] = fmaf(hv, w.x, acc[n][0]);
            acc[n][1] = fmaf(hv, w.y, acc[n][1]);
            acc[n][2] = fmaf(hv, w.z, acc[n][2]);
            acc[n][3] = fmaf(hv, w.w, acc[n][3]);
        }
    }

    #pragma unroll
    for (int n = 0; n < NPT; n++) {
        int node = node0 + nb + n;
        if (node >= NN) break;
        float4 r = make_float4(acc[n][0], acc[n][1], acc[n][2], acc[n][3]);
        if (HEAD) {
            float4 bb = __ldg(&((const float4*)bias)[colg]);
            r.x += bb.x; r.y += bb.y; r.z += bb.z; r.w += bb.w;
        }
        ((float4*)(mo + (size_t)node * COLS))[colg] = r;
    }
}

// ---------------- fused aggregate + epilogue ----------------
// One warp per dst node. acc = m[d]*dis[d]^2 + sum_e m[src]*nrm;
// h = relu(acc + b) + res.
__global__ __launch_bounds__(256) void k_aggr(
    const int* __restrict__ csrc, const float* __restrict__ cnrm,
    const unsigned* __restrict__ off, const float* __restrict__ dis,
    const float* __restrict__ m, const float* __restrict__ bias,
    const float* __restrict__ res, float* __restrict__ ho)
{
    int node = blockIdx.x * 8 + (threadIdx.x >> 5);
    if (node >= NN) return;
    const int lane = threadIdx.x & 31;

    const float4* m4 = (const float4*)m;
    unsigned e  = off[node];
    unsigned e1 = off[node + 1];

    float d  = dis[node];
    float d2 = d * d;
    float4 mm = m4[(size_t)node * 32 + lane];
    float4 acc = make_float4(mm.x * d2, mm.y * d2, mm.z * d2, mm.w * d2);

    // 2-deep software pipeline on (src, nrm) so the m-row load address is
    // ready one iteration early.
    int   s_nx = 0;
    float n_nx = 0.f;
    if (e < e1) { s_nx = __ldg(&csrc[e]); n_nx = __ldg(&cnrm[e]); }
    while (e < e1) {
        int   s  = s_nx;
        float nr = n_nx;
        unsigned en = e + 1;
        if (en < e1) { s_nx = __ldg(&csrc[en]); n_nx = __ldg(&cnrm[en]); }
        float4 v = m4[(size_t)s * 32 + lane];
        acc.x = fmaf(v.x, nr, acc.x);
        acc.y = fmaf(v.y, nr, acc.y);
        acc.z = fmaf(v.z, nr, acc.z);
        acc.w = fmaf(v.w, nr, acc.w);
        e = en;
    }

    float4 bb = __ldg(&((const float4*)bias)[lane]);
    float4 rr = ((const float4*)(res + (size_t)node * DH))[lane];
    float4 o;
    o.x = fmaxf(acc.x + bb.x, 0.f) + rr.x;
    o.y = fmaxf(acc.y + bb.y, 0.f) + rr.y;
    o.z = fmaxf(acc.z + bb.z, 0.f) + rr.z;
    o.w = fmaxf(acc.w + bb.w, 0.f) + rr.w;
    ((float4*)(ho + (size_t)node * DH))[lane] = o;
}

// ---------------- launch ----------------
extern "C" void kernel_launch(void* const* d_in, const int* in_sizes, int n_in,
                              void* d_out, int out_size) {
    const float* x  = (const float*)d_in[0];
    const void*  ei = d_in[1];
    const float* W1 = (const float*)d_in[2];
    const float* b1 = (const float*)d_in[3];
    const float* W2 = (const float*)d_in[4];
    const float* b2 = (const float*)d_in[5];
    const float* Wl = (const float*)d_in[6];
    const float* bl = (const float*)d_in[7];
    long long E = (long long)in_sizes[1] / 2;

    float *m, *h, *dis, *Wt1, *Wt2, *WtL, *cnrm;
    unsigned *deg, *part, *bsum, *off, *curs;
    int* csrc;
    cudaGetSymbolAddress((void**)&m,    g_m);
    cudaGetSymbolAddress((void**)&h,    g_h);
    cudaGetSymbolAddress((void**)&dis,  g_dis);
    cudaGetSymbolAddress((void**)&deg,  g_deg);
    cudaGetSymbolAddress((void**)&part, g_part);
    cudaGetSymbolAddress((void**)&bsum, g_bsum);
    cudaGetSymbolAddress((void**)&off,  g_off);
    cudaGetSymbolAddress((void**)&curs, g_curs);
    cudaGetSymbolAddress((void**)&csrc, g_csr_src);
    cudaGetSymbolAddress((void**)&cnrm, g_csr_nrm);
    cudaGetSymbolAddress((void**)&Wt1,  g_Wt1);
    cudaGetSymbolAddress((void**)&Wt2,  g_Wt2);
    cudaGetSymbolAddress((void**)&WtL,  g_WtL);

    // setup + CSR build (graph static across layers)
    k_init<<<(NN + 255) / 256, 256>>>(deg);
    k_detect<<<1, 256>>>((const int*)ei);
    k_deg<<<(unsigned)((E + 255) / 256), 256>>>(ei, E, deg);
    k_dis<<<(NN + 255) / 256, 256>>>(deg, dis);
    k_scan1<<<NB_SCAN, 1024>>>(deg, part, bsum);
    k_scan2<<<1, 128>>>(bsum);
    k_scan3<<<(NN + 255) / 256, 256>>>(deg, part, bsum, off, curs, E);
    k_place<<<(unsigned)((E + 255) / 256), 256>>>(ei, E, dis, curs, csrc, cnrm);

    k_transpose<<<(DH * DH + 255) / 256, 256>>>(W1, Wt1, DH, DH);
    k_transpose<<<(DH * DH + 255) / 256, 256>>>(W2, Wt2, DH, DH);
    k_transpose<<<(CC * DH + 255) / 256, 256>>>(Wl, WtL, CC, DH);

    const int gblocks = (NN + 63) / 64;
    const int ablocks = (NN + 7) / 8;

    // layer 1
    k_gemm<DH, 8, false><<<gblocks, 256>>>(x, Wt1, nullptr, m);
    k_aggr<<<ablocks, 256>>>(csrc, cnrm, off, dis, m, b1, x, h);

    // layer 2
    k_gemm<DH, 8, false><<<gblocks, 256>>>(h, Wt2, nullptr, m);
    k_aggr<<<ablocks, 256>>>(csrc, cnrm, off, dis, m, b2, h, h);

    // head
    k_gemm<CC, 4, true><<<gblocks, 256>>>(h, WtL, bl, (float*)d_out);
}

// round 7
// speedup vs baseline: 2.3560x; 1.3188x over previous
#include <cuda_runtime.h>
#include <cuda_bf16.h>
#include <cstdint>

#define NN 100000
#define EE 1600000
#define DH 128
#define CC 64
#define NB_SCAN 98          // ceil(NN/1024)
#define KP 136              // bf16 row stride (272B) -> conflict-free ldmatrix

// ---------------- device scratch (static, no allocs) ----------------
__device__ float    g_m[(size_t)NN * DH];    // m = h @ W^T
__device__ float    g_h[(size_t)NN * DH];    // layer activations
__device__ float    g_dis[NN];               // deg^{-1/2}
__device__ unsigned g_deg[NN];               // 1 + in-degree
__device__ unsigned g_part[NN];              // scan partials
__device__ unsigned g_bsum[NB_SCAN];
__device__ unsigned g_off[NN + 1];           // CSR offsets
__device__ unsigned g_curs[NN];              // placement cursors
__device__ int      g_csr_src[EE];
__device__ float    g_csr_nrm[EE];
__device__ int      g_is64;

// ---------------- PTX helpers (plain sm_103-safe) ----------------
__device__ __forceinline__ uint32_t smem_u32(const void* p) {
    uint32_t a;
    asm("{ .reg .u64 t; cvta.to.shared.u64 t, %1; cvt.u32.u64 %0, t; }"
        : "=r"(a) : "l"(p));
    return a;
}
__device__ __forceinline__ void ldsm_x4(uint32_t* r, uint32_t addr) {
    asm volatile("ldmatrix.sync.aligned.m8n8.x4.shared.b16 {%0,%1,%2,%3}, [%4];"
                 : "=r"(r[0]), "=r"(r[1]), "=r"(r[2]), "=r"(r[3]) : "r"(addr));
}
__device__ __forceinline__ void ldsm_x2(uint32_t* r, uint32_t addr) {
    asm volatile("ldmatrix.sync.aligned.m8n8.x2.shared.b16 {%0,%1}, [%2];"
                 : "=r"(r[0]), "=r"(r[1]) : "r"(addr));
}
__device__ __forceinline__ void mma_bf16(float* c, const uint32_t* a,
                                         const uint32_t* b) {
    asm volatile(
        "mma.sync.aligned.m16n8k16.row.col.f32.bf16.bf16.f32 "
        "{%0,%1,%2,%3}, {%4,%5,%6,%7}, {%8,%9}, {%0,%1,%2,%3};"
        : "+f"(c[0]), "+f"(c[1]), "+f"(c[2]), "+f"(c[3])
        : "r"(a[0]), "r"(a[1]), "r"(a[2]), "r"(a[3]), "r"(b[0]), "r"(b[1]));
}

// pack float4 -> hi bf16x2 pair + lo bf16x2 pair
__device__ __forceinline__ void split4(float4 v, uint2& hi, uint2& lo) {
    __nv_bfloat162 h01 = __floats2bfloat162_rn(v.x, v.y);
    __nv_bfloat162 h23 = __floats2bfloat162_rn(v.z, v.w);
    float lx = v.x - __bfloat162float(h01.x);
    float ly = v.y - __bfloat162float(h01.y);
    float lz = v.z - __bfloat162float(h23.x);
    float lw = v.w - __bfloat162float(h23.y);
    __nv_bfloat162 l01 = __floats2bfloat162_rn(lx, ly);
    __nv_bfloat162 l23 = __floats2bfloat162_rn(lz, lw);
    hi.x = *(uint32_t*)&h01; hi.y = *(uint32_t*)&h23;
    lo.x = *(uint32_t*)&l01; lo.y = *(uint32_t*)&l23;
}

// ---------------- setup ----------------
__global__ void k_init(unsigned* deg) {
    int i = blockIdx.x * blockDim.x + threadIdx.x;
    if (i < NN) deg[i] = 1u;                 // self-loop
    if (i == 0) g_is64 = 1;
}
__global__ void k_detect(const int* __restrict__ w) {
    if (w[2 * threadIdx.x + 1] != 0) g_is64 = 0;
}
__device__ __forceinline__ int edge_idx(const void* ei, long long i) {
    if (g_is64) return (int)((const long long*)ei)[i];
    return ((const int*)ei)[i];
}
__global__ void k_deg(const void* __restrict__ ei, long long E, unsigned* deg) {
    long long i = (long long)blockIdx.x * blockDim.x + threadIdx.x;
    if (i < E) atomicAdd(&deg[edge_idx(ei, E + i)], 1u);
}
__global__ void k_dis(const unsigned* __restrict__ deg, float* __restrict__ dis) {
    int i = blockIdx.x * blockDim.x + threadIdx.x;
    if (i < NN) dis[i] = rsqrtf((float)deg[i]);
}

// ---------------- CSR build ----------------
__global__ __launch_bounds__(1024) void k_scan1(const unsigned* __restrict__ deg,
                                                unsigned* __restrict__ part,
                                                unsigned* __restrict__ bsum) {
    __shared__ unsigned ws[32];
    int t = threadIdx.x;
    int i = blockIdx.x * 1024 + t;
    unsigned x = (i < NN) ? (deg[i] - 1u) : 0u;
    #pragma unroll
    for (int o = 1; o < 32; o <<= 1) {
        unsigned y = __shfl_up_sync(~0u, x, o);
        if ((t & 31) >= o) x += y;
    }
    if ((t & 31) == 31) ws[t >> 5] = x;
    __syncthreads();
    if (t < 32) {
        unsigned w = ws[t];
        #pragma unroll
        for (int o = 1; o < 32; o <<= 1) {
            unsigned y = __shfl_up_sync(~0u, w, o);
            if (t >= o) w += y;
        }
        ws[t] = w;
    }
    __syncthreads();
    if (t >= 32) x += ws[(t >> 5) - 1];
    if (i < NN) part[i] = x;
    if (t == 1023) bsum[blockIdx.x] = x;
}
__global__ void k_scan2(unsigned* __restrict__ bsum) {
    __shared__ unsigned s[NB_SCAN];
    int t = threadIdx.x;
    if (t < NB_SCAN) s[t] = bsum[t];
    __syncthreads();
    if (t == 0) {
        unsigned run = 0;
        for (int k = 0; k < NB_SCAN; k++) { unsigned v = s[k]; s[k] = run; run += v; }
    }
    __syncthreads();
    if (t < NB_SCAN) bsum[t] = s[t];
}
__global__ void k_scan3(const unsigned* __restrict__ deg,
                        const unsigned* __restrict__ part,
                        const unsigned* __restrict__ bsum,
                        unsigned* __restrict__ off, unsigned* __restrict__ curs,
                        long long E) {
    int i = blockIdx.x * blockDim.x + threadIdx.x;
    if (i < NN) {
        unsigned incl = part[i] + bsum[i >> 10];
        unsigned excl = incl - (deg[i] - 1u);
        off[i] = excl;
        curs[i] = excl;
    }
    if (i == 0) off[NN] = (unsigned)E;
}
__global__ void k_place(const void* __restrict__ ei, long long E,
                        const float* __restrict__ dis, unsigned* __restrict__ curs,
                        int* __restrict__ csrc, float* __restrict__ cnrm) {
    long long i = (long long)blockIdx.x * blockDim.x + threadIdx.x;
    if (i >= E) return;
    int s = edge_idx(ei, i);
    int d = edge_idx(ei, E + i);
    unsigned pos = atomicAdd(&curs[d], 1u);
    csrc[pos] = s;
    cnrm[pos] = dis[s] * dis[d];
}

// ---------------- bf16 split-3 HMMA GEMM: out = hin @ W^T ----------------
// Tile M=128 x N=NT, K=128 resident. 8 warps: warp tile 32 x (NT/2).
// A*B ~= Ahi*Bhi + Ahi*Blo + Alo*Bhi; residual ~2^-18 relative.
template <int NT, bool HEAD>
__global__ __launch_bounds__(256) void k_mm(
    const float* __restrict__ hin, const float* __restrict__ W,   // W: [NT][128]
    const float* __restrict__ bias, float* __restrict__ out)
{
    extern __shared__ char smem[];
    constexpr int APL = 128 * KP * 2;            // one A plane (bytes)
    constexpr int BPL = NT * KP * 2;             // one B plane
    const int AH = 0, AL = APL, BH = 2 * APL, BL = 2 * APL + BPL;
    constexpr int WN = NT / 2;                   // warp n-extent
    constexpr int NTI = WN / 8;                  // n8-tiles per warp

    const uint32_t sb = smem_u32(smem);
    const int t = threadIdx.x;
    const int w = t >> 5, lane = t & 31;
    const int node0 = blockIdx.x * 128;

    // ---- stage A (128 x 128) ----
    #pragma unroll
    for (int idx = t; idx < 128 * 32; idx += 256) {
        int row = idx >> 5, kq = idx & 31;
        int node = node0 + row;
        float4 v = make_float4(0.f, 0.f, 0.f, 0.f);
        if (node < NN) v = __ldg((const float4*)(hin + (size_t)node * 128 + kq * 4));
        uint2 hi, lo;
        split4(v, hi, lo);
        int boff = (row * KP + kq * 4) * 2;
        *(uint2*)(smem + AH + boff) = hi;
        *(uint2*)(smem + AL + boff) = lo;
    }
    // ---- stage B = W (NT x 128) ----
    #pragma unroll
    for (int idx = t; idx < NT * 32; idx += 256) {
        int row = idx >> 5, kq = idx & 31;
        float4 v = __ldg((const float4*)(W + (size_t)row * 128 + kq * 4));
        uint2 hi, lo;
        split4(v, hi, lo);
        int boff = (row * KP + kq * 4) * 2;
        *(uint2*)(smem + BH + boff) = hi;
        *(uint2*)(smem + BL + boff) = lo;
    }
    __syncthreads();

    // ---- compute ----
    const int wm = w >> 1, wn = w & 1;
    float acc[2][NTI][4];
    #pragma unroll
    for (int mi = 0; mi < 2; mi++)
        #pragma unroll
        for (int ni = 0; ni < NTI; ni++)
            #pragma unroll
            for (int j = 0; j < 4; j++) acc[mi][ni][j] = 0.f;

    // ldmatrix lane address components
    const int tl = lane >> 3, r8 = lane & 7;
    // A x4: row = wm*32 + mi*16 + (tl&1)*8 + r8 ; col = k0 + (tl>>1)*8
    const uint32_t arow = (uint32_t)((wm * 32 + (tl & 1) * 8 + r8) * KP + (tl >> 1) * 8) * 2;
    // B x2: row = wn*WN + ni*8 + r8 ; col = k0 + (tl&1)*8
    const uint32_t brow = (uint32_t)((wn * WN + r8) * KP + (tl & 1) * 8) * 2;

    #pragma unroll
    for (int ks = 0; ks < 8; ks++) {
        const uint32_t kof = (uint32_t)(ks * 16) * 2;
        uint32_t ah[2][4], al[2][4];
        #pragma unroll
        for (int mi = 0; mi < 2; mi++) {
            uint32_t ad = sb + arow + (uint32_t)(mi * 16 * KP) * 2 + kof;
            ldsm_x4(ah[mi], ad + AH);
            ldsm_x4(al[mi], ad + AL);
        }
        #pragma unroll
        for (int ni = 0; ni < NTI; ni++) {
            uint32_t bd = sb + brow + (uint32_t)(ni * 8 * KP) * 2 + kof;
            uint32_t bh[2], bl[2];
            ldsm_x2(bh, bd + BH);
            ldsm_x2(bl, bd + BL);
            #pragma unroll
            for (int mi = 0; mi < 2; mi++) {
                mma_bf16(acc[mi][ni], ah[mi], bh);
                mma_bf16(acc[mi][ni], ah[mi], bl);
                mma_bf16(acc[mi][ni], al[mi], bh);
            }
        }
    }

    // ---- epilogue ----
    const int g = lane >> 2, tg = lane & 3;
    #pragma unroll
    for (int mi = 0; mi < 2; mi++) {
        int rb = node0 + wm * 32 + mi * 16;
        #pragma unroll
        for (int ni = 0; ni < NTI; ni++) {
            int col = wn * WN + ni * 8 + tg * 2;
            float2 c01 = make_float2(acc[mi][ni][0], acc[mi][ni][1]);
            float2 c23 = make_float2(acc[mi][ni][2], acc[mi][ni][3]);
            if (HEAD) {
                float2 bb = *(const float2*)(bias + col);
                c01.x += bb.x; c01.y += bb.y;
                c23.x += bb.x; c23.y += bb.y;
            }
            int n1 = rb + g, n2 = rb + g + 8;
            if (n1 < NN) *(float2*)(out + (size_t)n1 * NT + col) = c01;
            if (n2 < NN) *(float2*)(out + (size_t)n2 * NT + col) = c23;
        }
    }
}

// ---------------- fused aggregate + epilogue ----------------
__global__ __launch_bounds__(256) void k_aggr(
    const int* __restrict__ csrc, const float* __restrict__ cnrm,
    const unsigned* __restrict__ off, const float* __restrict__ dis,
    const float* __restrict__ m, const float* __restrict__ bias,
    const float* __restrict__ res, float* __restrict__ ho)
{
    int node = blockIdx.x * 8 + (threadIdx.x >> 5);
    if (node >= NN) return;
    const int lane = threadIdx.x & 31;

    const float4* m4 = (const float4*)m;
    unsigned e = off[node];
    unsigned e1 = off[node + 1];

    float d = dis[node];
    float d2 = d * d;
    float4 mm = m4[(size_t)node * 32 + lane];
    float4 acc = make_float4(mm.x * d2, mm.y * d2, mm.z * d2, mm.w * d2);

    int s_nx = 0;
    float n_nx = 0.f;
    if (e < e1) { s_nx = __ldg(&csrc[e]); n_nx = __ldg(&cnrm[e]); }
    while (e < e1) {
        int s = s_nx;
        float nr = n_nx;
        unsigned en = e + 1;
        if (en < e1) { s_nx = __ldg(&csrc[en]); n_nx = __ldg(&cnrm[en]); }
        float4 v = m4[(size_t)s * 32 + lane];
        acc.x = fmaf(v.x, nr, acc.x);
        acc.y = fmaf(v.y, nr, acc.y);
        acc.z = fmaf(v.z, nr, acc.z);
        acc.w = fmaf(v.w, nr, acc.w);
        e = en;
    }

    float4 bb = __ldg(&((const float4*)bias)[lane]);
    float4 rr = ((const float4*)(res + (size_t)node * DH))[lane];
    float4 o;
    o.x = fmaxf(acc.x + bb.x, 0.f) + rr.x;
    o.y = fmaxf(acc.y + bb.y, 0.f) + rr.y;
    o.z = fmaxf(acc.z + bb.z, 0.f) + rr.z;
    o.w = fmaxf(acc.w + bb.w, 0.f) + rr.w;
    ((float4*)(ho + (size_t)node * DH))[lane] = o;
}

// ---------------- launch ----------------
extern "C" void kernel_launch(void* const* d_in, const int* in_sizes, int n_in,
                              void* d_out, int out_size) {
    const float* x  = (const float*)d_in[0];
    const void*  ei = d_in[1];
    const float* W1 = (const float*)d_in[2];
    const float* b1 = (const float*)d_in[3];
    const float* W2 = (const float*)d_in[4];
    const float* b2 = (const float*)d_in[5];
    const float* Wl = (const float*)d_in[6];
    const float* bl = (const float*)d_in[7];
    long long E = (long long)in_sizes[1] / 2;

    float *m, *h, *dis, *cnrm;
    unsigned *deg, *part, *bsum, *off, *curs;
    int* csrc;
    cudaGetSymbolAddress((void**)&m,    g_m);
    cudaGetSymbolAddress((void**)&h,    g_h);
    cudaGetSymbolAddress((void**)&dis,  g_dis);
    cudaGetSymbolAddress((void**)&deg,  g_deg);
    cudaGetSymbolAddress((void**)&part, g_part);
    cudaGetSymbolAddress((void**)&bsum, g_bsum);
    cudaGetSymbolAddress((void**)&off,  g_off);
    cudaGetSymbolAddress((void**)&curs, g_curs);
    cudaGetSymbolAddress((void**)&csrc, g_csr_src);
    cudaGetSymbolAddress((void**)&cnrm, g_csr_nrm);

    const int SMEM_L = 2 * (128 * KP * 2) + 2 * (DH * KP * 2);  // 139264
    const int SMEM_H = 2 * (128 * KP * 2) + 2 * (CC * KP * 2);  // 104448
    cudaFuncSetAttribute(k_mm<DH, false>, cudaFuncAttributeMaxDynamicSharedMemorySize, SMEM_L);
    cudaFuncSetAttribute(k_mm<CC, true>,  cudaFuncAttributeMaxDynamicSharedMemorySize, SMEM_H);

    // setup + CSR build
    k_init<<<(NN + 255) / 256, 256>>>(deg);
    k_detect<<<1, 256>>>((const int*)ei);
    k_deg<<<(unsigned)((E + 255) / 256), 256>>>(ei, E, deg);
    k_dis<<<(NN + 255) / 256, 256>>>(deg, dis);
    k_scan1<<<NB_SCAN, 1024>>>(deg, part, bsum);
    k_scan2<<<1, 128>>>(bsum);
    k_scan3<<<(NN + 255) / 256, 256>>>(deg, part, bsum, off, curs, E);
    k_place<<<(unsigned)((E + 255) / 256), 256>>>(ei, E, dis, curs, csrc, cnrm);

    const int mblocks = (NN + 127) / 128;   // 782
    const int ablocks = (NN + 7) / 8;

    // layer 1
    k_mm<DH, false><<<mblocks, 256, SMEM_L>>>(x, W1, nullptr, m);
    k_aggr<<<ablocks, 256>>>(csrc, cnrm, off, dis, m, b1, x, h);

    // layer 2
    k_mm<DH, false><<<mblocks, 256, SMEM_L>>>(h, W2, nullptr, m);
    k_aggr<<<ablocks, 256>>>(csrc, cnrm, off, dis, m, b2, h, h);

    // head
    k_mm<CC, true><<<mblocks, 256, SMEM_H>>>(h, Wl, bl, (float*)d_out);
}

// round 8
// speedup vs baseline: 2.4051x; 1.0208x over previous
#include <cuda_runtime.h>
#include <cuda_bf16.h>
#include <cstdint>

#define NN 100000
#define EE 1600000
#define DH 128
#define CC 64
#define NB_SCAN 98          // ceil(NN/1024)
#define KP 136              // bf16 row stride (272B) -> conflict-free ldmatrix

// ---------------- device scratch (static, no allocs) ----------------
__device__ float    g_m[(size_t)NN * DH];    // m = h @ W^T
__device__ float    g_h[(size_t)NN * DH];    // layer activations
__device__ float    g_dis[NN];               // deg^{-1/2}
__device__ unsigned g_deg[NN];               // 1 + in-degree
__device__ unsigned g_part[NN];              // scan partials
__device__ unsigned g_bsum[NB_SCAN];
__device__ unsigned g_off[NN + 1];           // CSR offsets
__device__ unsigned g_curs[NN];              // placement cursors
__device__ int2     g_edge[EE];              // {src, bitcast(nrm)}
__device__ uint4    g_wf1[8 * 16 * 32];      // W1 mma B-fragments (hi,lo)
__device__ uint4    g_wf2[8 * 16 * 32];
__device__ uint4    g_wfl[8 * 8 * 32];
__device__ int      g_is64;

// ---------------- PTX helpers (plain sm_103-safe) ----------------
__device__ __forceinline__ uint32_t smem_u32(const void* p) {
    uint32_t a;
    asm("{ .reg .u64 t; cvta.to.shared.u64 t, %1; cvt.u32.u64 %0, t; }"
        : "=r"(a) : "l"(p));
    return a;
}
__device__ __forceinline__ void ldsm_x4(uint32_t* r, uint32_t addr) {
    asm volatile("ldmatrix.sync.aligned.m8n8.x4.shared.b16 {%0,%1,%2,%3}, [%4];"
                 : "=r"(r[0]), "=r"(r[1]), "=r"(r[2]), "=r"(r[3]) : "r"(addr));
}
__device__ __forceinline__ void mma_bf16(float* c, const uint32_t* a,
                                         const uint32_t* b) {
    asm volatile(
        "mma.sync.aligned.m16n8k16.row.col.f32.bf16.bf16.f32 "
        "{%0,%1,%2,%3}, {%4,%5,%6,%7}, {%8,%9}, {%0,%1,%2,%3};"
        : "+f"(c[0]), "+f"(c[1]), "+f"(c[2]), "+f"(c[3])
        : "r"(a[0]), "r"(a[1]), "r"(a[2]), "r"(a[3]), "r"(b[0]), "r"(b[1]));
}

// pack float4 -> hi bf16x2 pair + lo bf16x2 pair
__device__ __forceinline__ void split4(float4 v, uint2& hi, uint2& lo) {
    __nv_bfloat162 h01 = __floats2bfloat162_rn(v.x, v.y);
    __nv_bfloat162 h23 = __floats2bfloat162_rn(v.z, v.w);
    float lx = v.x - __bfloat162float(h01.x);
    float ly = v.y - __bfloat162float(h01.y);
    float lz = v.z - __bfloat162float(h23.x);
    float lw = v.w - __bfloat162float(h23.y);
    __nv_bfloat162 l01 = __floats2bfloat162_rn(lx, ly);
    __nv_bfloat162 l23 = __floats2bfloat162_rn(lz, lw);
    hi.x = *(uint32_t*)&h01; hi.y = *(uint32_t*)&h23;
    lo.x = *(uint32_t*)&l01; lo.y = *(uint32_t*)&l23;
}

// ---------------- setup ----------------
__global__ void k_detect(const int* __restrict__ w) {
    bool nz = (w[2 * threadIdx.x + 1] != 0);
    int any = __syncthreads_or((int)nz);
    if (threadIdx.x == 0) g_is64 = !any;     // int64 values < 2^31 -> odd words 0
}
__global__ void k_init(unsigned* deg) {
    int i = blockIdx.x * blockDim.x + threadIdx.x;
    if (i < NN) deg[i] = 1u;                 // self-loop
}
__device__ __forceinline__ int edge_idx(const void* ei, long long i) {
    if (g_is64) return (int)((const long long*)ei)[i];
    return ((const int*)ei)[i];
}
__global__ void k_deg(const void* __restrict__ ei, long long E, unsigned* deg) {
    long long i = (long long)blockIdx.x * blockDim.x + threadIdx.x;
    if (i < E) atomicAdd(&deg[edge_idx(ei, E + i)], 1u);
}

// precompute mma B-fragments for all three weight matrices
__global__ void k_wfrag(const float* __restrict__ W1, const float* __restrict__ W2,
                        const float* __restrict__ Wl,
                        uint4* __restrict__ f1, uint4* __restrict__ f2,
                        uint4* __restrict__ fl) {
    int i = blockIdx.x * blockDim.x + threadIdx.x;
    const float* W; uint4* F; int NT8, j;
    if (i < 4096)        { W = W1; F = f1; NT8 = 16; j = i; }
    else if (i < 8192)   { W = W2; F = f2; NT8 = 16; j = i - 4096; }
    else if (i < 10240)  { W = Wl; F = fl; NT8 = 8;  j = i - 8192; }
    else return;
    int lane = j & 31, t = j >> 5;
    int ni = t % NT8, ks = t / NT8;
    int n = ni * 8 + (lane >> 2);
    int k = ks * 16 + (lane & 3) * 2;
    const float* r = W + (size_t)n * 128;
    float w0 = r[k], w1 = r[k + 1], w2 = r[k + 8], w3 = r[k + 9];
    uint2 hi, lo;
    split4(make_float4(w0, w1, w2, w3), hi, lo);  // hi.x=(w0,w1) hi.y=(w2,w3)
    F[j] = make_uint4(hi.x, hi.y, lo.x, lo.y);    // {b0hi, b1hi, b0lo, b1lo}
}

// ---------------- CSR build ----------------
__global__ __launch_bounds__(1024) void k_scan1(const unsigned* __restrict__ deg,
                                                unsigned* __restrict__ part,
                                                unsigned* __restrict__ bsum) {
    __shared__ unsigned ws[32];
    int t = threadIdx.x;
    int i = blockIdx.x * 1024 + t;
    unsigned x = (i < NN) ? (deg[i] - 1u) : 0u;
    #pragma unroll
    for (int o = 1; o < 32; o <<= 1) {
        unsigned y = __shfl_up_sync(~0u, x, o);
        if ((t & 31) >= o) x += y;
    }
    if ((t & 31) == 31) ws[t >> 5] = x;
    __syncthreads();
    if (t < 32) {
        unsigned w = ws[t];
        #pragma unroll
        for (int o = 1; o < 32; o <<= 1) {
            unsigned y = __shfl_up_sync(~0u, w, o);
            if (t >= o) w += y;
        }
        ws[t] = w;
    }
    __syncthreads();
    if (t >= 32) x += ws[(t >> 5) - 1];
    if (i < NN) part[i] = x;
    if (t == 1023) bsum[blockIdx.x] = x;
}
__global__ void k_scan2(unsigned* __restrict__ bsum) {
    __shared__ unsigned s[NB_SCAN];
    int t = threadIdx.x;
    if (t < NB_SCAN) s[t] = bsum[t];
    __syncthreads();
    if (t == 0) {
        unsigned run = 0;
        for (int k = 0; k < NB_SCAN; k++) { unsigned v = s[k]; s[k] = run; run += v; }
    }
    __syncthreads();
    if (t < NB_SCAN) bsum[t] = s[t];
}
__global__ void k_scan3(const unsigned* __restrict__ deg,
                        const unsigned* __restrict__ part,
                        const unsigned* __restrict__ bsum,
                        unsigned* __restrict__ off, unsigned* __restrict__ curs,
                        float* __restrict__ dis, long long E) {
    int i = blockIdx.x * blockDim.x + threadIdx.x;
    if (i < NN) {
        unsigned dg = deg[i];
        unsigned incl = part[i] + bsum[i >> 10];
        unsigned excl = incl - (dg - 1u);
        off[i] = excl;
        curs[i] = excl;
        dis[i] = rsqrtf((float)dg);          // fused k_dis
    }
    if (i == 0) off[NN] = (unsigned)E;
}
__global__ void k_place(const void* __restrict__ ei, long long E,
                        const float* __restrict__ dis, unsigned* __restrict__ curs,
                        int2* __restrict__ edges) {
    long long i = (long long)blockIdx.x * blockDim.x + threadIdx.x;
    if (i >= E) return;
    int s = edge_idx(ei, i);
    int d = edge_idx(ei, E + i);
    unsigned pos = atomicAdd(&curs[d], 1u);
    float nrm = dis[s] * dis[d];
    edges[pos] = make_int2(s, __float_as_int(nrm));
}

// ---------------- bf16 split-3 HMMA GEMM: out = hin @ W^T ----------------
// Tile M=128 x N=NT, K=128 resident in smem (A only; B-fragments from global).
// 8 warps: warp tile 32 x (NT/2). A*B ~= Ahi*Bhi + Ahi*Blo + Alo*Bhi.
template <int NT, bool HEAD>
__global__ __launch_bounds__(256) void k_mm(
    const float* __restrict__ hin, const uint4* __restrict__ frag,
    const float* __restrict__ bias, float* __restrict__ out)
{
    extern __shared__ char smem[];
    constexpr int APL = 128 * KP * 2;            // one A plane (bytes)
    const int AH = 0, AL = APL;
    constexpr int WN = NT / 2;                   // warp n-extent
    constexpr int NTI = WN / 8;                  // n8-tiles per warp
    constexpr int NT8 = NT / 8;

    const uint32_t sb = smem_u32(smem);
    const int t = threadIdx.x;
    const int w = t >> 5, lane = t & 31;
    const int node0 = blockIdx.x * 128;

    // ---- stage A (128 x 128) as hi/lo bf16 planes ----
    #pragma unroll
    for (int idx = t; idx < 128 * 32; idx += 256) {
        int row = idx >> 5, kq = idx & 31;
        int node = node0 + row;
        float4 v = make_float4(0.f, 0.f, 0.f, 0.f);
        if (node < NN) v = __ldg((const float4*)(hin + (size_t)node * 128 + kq * 4));
        uint2 hi, lo;
        split4(v, hi, lo);
        int boff = (row * KP + kq * 4) * 2;
        *(uint2*)(smem + AH + boff) = hi;
        *(uint2*)(smem + AL + boff) = lo;
    }
    __syncthreads();

    // ---- compute ----
    const int wm = w >> 1, wn = w & 1;
    float acc[2][NTI][4];
    #pragma unroll
    for (int mi = 0; mi < 2; mi++)
        #pragma unroll
        for (int ni = 0; ni < NTI; ni++)
            #pragma unroll
            for (int j = 0; j < 4; j++) acc[mi][ni][j] = 0.f;

    const int tl = lane >> 3, r8 = lane & 7;
    // A x4: row = wm*32 + mi*16 + (tl&1)*8 + r8 ; col = k0 + (tl>>1)*8
    const uint32_t arow = (uint32_t)((wm * 32 + (tl & 1) * 8 + r8) * KP + (tl >> 1) * 8) * 2;

    #pragma unroll
    for (int ks = 0; ks < 8; ks++) {
        const uint32_t kof = (uint32_t)(ks * 16) * 2;
        uint32_t ah[2][4], al[2][4];
        #pragma unroll
        for (int mi = 0; mi < 2; mi++) {
            uint32_t ad = sb + arow + (uint32_t)(mi * 16 * KP) * 2 + kof;
            ldsm_x4(ah[mi], ad + AH);
            ldsm_x4(al[mi], ad + AL);
        }
        #pragma unroll
        for (int ni = 0; ni < NTI; ni++) {
            uint4 f = __ldg(&frag[(size_t)((ks * NT8 + wn * NTI + ni) * 32 + lane)]);
            uint32_t bh[2] = {f.x, f.y};
            uint32_t bl[2] = {f.z, f.w};
            #pragma unroll
            for (int mi = 0; mi < 2; mi++) {
                mma_bf16(acc[mi][ni], ah[mi], bh);
                mma_bf16(acc[mi][ni], ah[mi], bl);
                mma_bf16(acc[mi][ni], al[mi], bh);
            }
        }
    }

    // ---- epilogue ----
    const int g = lane >> 2, tg = lane & 3;
    #pragma unroll
    for (int mi = 0; mi < 2; mi++) {
        int rb = node0 + wm * 32 + mi * 16;
        #pragma unroll
        for (int ni = 0; ni < NTI; ni++) {
            int col = wn * WN + ni * 8 + tg * 2;
            float2 c01 = make_float2(acc[mi][ni][0], acc[mi][ni][1]);
            float2 c23 = make_float2(acc[mi][ni][2], acc[mi][ni][3]);
            if (HEAD) {
                float2 bb = *(const float2*)(bias + col);
                c01.x += bb.x; c01.y += bb.y;
                c23.x += bb.x; c23.y += bb.y;
            }
            int n1 = rb + g, n2 = rb + g + 8;
            if (n1 < NN) *(float2*)(out + (size_t)n1 * NT + col) = c01;
            if (n2 < NN) *(float2*)(out + (size_t)n2 * NT + col) = c23;
        }
    }
}

// ---------------- fused aggregate + epilogue ----------------
// One warp per dst node; 2-way unrolled edge loop (dual accumulators -> MLP 2).
__global__ __launch_bounds__(256) void k_aggr(
    const int2* __restrict__ edges, const unsigned* __restrict__ off,
    const float* __restrict__ dis, const float* __restrict__ m,
    const float* __restrict__ bias, const float* __restrict__ res,
    float* __restrict__ ho)
{
    int node = blockIdx.x * 8 + (threadIdx.x >> 5);
    if (node >= NN) return;
    const int lane = threadIdx.x & 31;

    const float4* m4 = (const float4*)m;
    unsigned e0 = off[node];
    unsigned cnt = off[node + 1] - e0;
    const int2* ep = edges + e0;

    float d = dis[node];
    float d2 = d * d;
    float4 mm = m4[(size_t)node * 32 + lane];
    float4 acc  = make_float4(mm.x * d2, mm.y * d2, mm.z * d2, mm.w * d2);
    float4 acc2 = make_float4(0.f, 0.f, 0.f, 0.f);

    unsigned k = 0;
    for (; k + 2 <= cnt; k += 2) {
        int2 ea = __ldg(&ep[k]);
        int2 eb = __ldg(&ep[k + 1]);
        float4 va = m4[(size_t)ea.x * 32 + lane];
        float4 vb = m4[(size_t)eb.x * 32 + lane];
        float na = __int_as_float(ea.y);
        float nb = __int_as_float(eb.y);
        acc.x  = fmaf(va.x, na, acc.x);
        acc.y  = fmaf(va.y, na, acc.y);
        acc.z  = fmaf(va.z, na, acc.z);
        acc.w  = fmaf(va.w, na, acc.w);
        acc2.x = fmaf(vb.x, nb, acc2.x);
        acc2.y = fmaf(vb.y, nb, acc2.y);
        acc2.z = fmaf(vb.z, nb, acc2.z);
        acc2.w = fmaf(vb.w, nb, acc2.w);
    }
    if (k < cnt) {
        int2 ea = __ldg(&ep[k]);
        float4 va = m4[(size_t)ea.x * 32 + lane];
        float na = __int_as_float(ea.y);
        acc.x = fmaf(va.x, na, acc.x);
        acc.y = fmaf(va.y, na, acc.y);
        acc.z = fmaf(va.z, na, acc.z);
        acc.w = fmaf(va.w, na, acc.w);
    }
    acc.x += acc2.x; acc.y += acc2.y; acc.z += acc2.z; acc.w += acc2.w;

    float4 bb = __ldg(&((const float4*)bias)[lane]);
    float4 rr = ((const float4*)(res + (size_t)node * DH))[lane];
    float4 o;
    o.x = fmaxf(acc.x + bb.x, 0.f) + rr.x;
    o.y = fmaxf(acc.y + bb.y, 0.f) + rr.y;
    o.z = fmaxf(acc.z + bb.z, 0.f) + rr.z;
    o.w = fmaxf(acc.w + bb.w, 0.f) + rr.w;
    ((float4*)(ho + (size_t)node * DH))[lane] = o;
}

// ---------------- launch ----------------
extern "C" void kernel_launch(void* const* d_in, const int* in_sizes, int n_in,
                              void* d_out, int out_size) {
    const float* x  = (const float*)d_in[0];
    const void*  ei = d_in[1];
    const float* W1 = (const float*)d_in[2];
    const float* b1 = (const float*)d_in[3];
    const float* W2 = (const float*)d_in[4];
    const float* b2 = (const float*)d_in[5];
    const float* Wl = (const float*)d_in[6];
    const float* bl = (const float*)d_in[7];
    long long E = (long long)in_sizes[1] / 2;

    float *m, *h, *dis;
    unsigned *deg, *part, *bsum, *off, *curs;
    int2* edges;
    uint4 *wf1, *wf2, *wfl;
    cudaGetSymbolAddress((void**)&m,     g_m);
    cudaGetSymbolAddress((void**)&h,     g_h);
    cudaGetSymbolAddress((void**)&dis,   g_dis);
    cudaGetSymbolAddress((void**)&deg,   g_deg);
    cudaGetSymbolAddress((void**)&part,  g_part);
    cudaGetSymbolAddress((void**)&bsum,  g_bsum);
    cudaGetSymbolAddress((void**)&off,   g_off);
    cudaGetSymbolAddress((void**)&curs,  g_curs);
    cudaGetSymbolAddress((void**)&edges, g_edge);
    cudaGetSymbolAddress((void**)&wf1,   g_wf1);
    cudaGetSymbolAddress((void**)&wf2,   g_wf2);
    cudaGetSymbolAddress((void**)&wfl,   g_wfl);

    const int SMEM_MM = 2 * (128 * KP * 2);      // 69632 (A planes only)
    cudaFuncSetAttribute(k_mm<DH, false>, cudaFuncAttributeMaxDynamicSharedMemorySize, SMEM_MM);
    cudaFuncSetAttribute(k_mm<CC, true>,  cudaFuncAttributeMaxDynamicSharedMemorySize, SMEM_MM);

    // setup + CSR build
    k_detect<<<1, 256>>>((const int*)ei);
    k_init<<<(NN + 255) / 256, 256>>>(deg);
    k_wfrag<<<(10240 + 255) / 256, 256>>>(W1, W2, Wl, wf1, wf2, wfl);
    k_deg<<<(unsigned)((E + 255) / 256), 256>>>(ei, E, deg);
    k_scan1<<<NB_SCAN, 1024>>>(deg, part, bsum);
    k_scan2<<<1, 128>>>(bsum);
    k_scan3<<<(NN + 255) / 256, 256>>>(deg, part, bsum, off, curs, dis, E);
    k_place<<<(unsigned)((E + 255) / 256), 256>>>(ei, E, dis, curs, edges);

    const int mblocks = (NN + 127) / 128;   // 782
    const int ablocks = (NN + 7) / 8;

    // layer 1
    k_mm<DH, false><<<mblocks, 256, SMEM_MM>>>(x, wf1, nullptr, m);
    k_aggr<<<ablocks, 256>>>(edges, off, dis, m, b1, x, h);

    // layer 2
    k_mm<DH, false><<<mblocks, 256, SMEM_MM>>>(h, wf2, nullptr, m);
    k_aggr<<<ablocks, 256>>>(edges, off, dis, m, b2, h, h);

    // head
    k_mm<CC, true><<<mblocks, 256, SMEM_MM>>>(h, wfl, bl, (float*)d_out);
}